// round 9
// baseline (speedup 1.0000x reference)
#include <cuda_runtime.h>
#include <cstdint>

#define N_NODES 40000
#define N_EDGES 640000
#define IN_DIM  128
#define HID     256

#define SCAN_BLOCKS 40
#define SCAN_CHUNK  1000   // 40 * 1000 = 40000 exactly

// ---------------- device scratch (static, no allocations) ----------------
__device__ int   g_is64;
__device__ int   g_srcs[N_EDGES];
__device__ int   g_dsts[N_EDGES];
__device__ int   g_count[N_NODES];
__device__ int   g_rowstart[N_NODES + 1];
__device__ int   g_cursor[N_NODES];
__device__ int   g_src[N_EDGES];
__device__ int   g_blocksum[SCAN_BLOCKS];
__device__ int   g_blockoff[SCAN_BLOCKS];
__device__ __align__(16) float g_agg[(size_t)N_NODES * HID];
__device__ __align__(16) float g_h  [(size_t)N_NODES * HID];
__device__ __align__(16) float g_h2 [(size_t)N_NODES * HID];
__device__ __align__(16) float g_R  [(size_t)N_NODES * HID];   // Wr-half result
__device__ __align__(16) float g_xr [(size_t)N_NODES * IN_DIM];
__device__ __align__(16) float g_wr [2 * HID * IN_DIM + 4 * HID * HID];

#define WO_L1 0
#define WO_R1 (HID * IN_DIM)
#define WO_L2 (2 * HID * IN_DIM)
#define WO_R2 (2 * HID * IN_DIM + HID * HID)
#define WO_L3 (2 * HID * IN_DIM + 2 * HID * HID)
#define WO_R3 (2 * HID * IN_DIM + 3 * HID * HID)
#define W_TOTAL (2 * HID * IN_DIM + 4 * HID * HID)

__device__ __forceinline__ uint32_t f2tf32(float v) {
    uint32_t o;
    asm("cvt.rna.tf32.f32 %0, %1;" : "=r"(o) : "f"(v));
    return o;
}
__device__ __forceinline__ float roundtf(float v) { return __uint_as_float(f2tf32(v)); }

// ---------------- edge-index dtype detection ----------------
__global__ void k_detect(const int* __restrict__ ei_w) {
    __shared__ int acc;
    if (threadIdx.x == 0) acc = 0;
    __syncthreads();
    int v = 0;
    for (int i = threadIdx.x; i < 2048; i += 256) v |= ei_w[2 * i + 1];
    atomicOr(&acc, v);
    __syncthreads();
    if (threadIdx.x == 0) g_is64 = (acc == 0) ? 1 : 0;
}

__device__ __forceinline__ int clampN(int v) {
    return v < 0 ? 0 : (v >= N_NODES ? N_NODES - 1 : v);
}

__global__ void k_zero_counts() {
    int i = blockIdx.x * blockDim.x + threadIdx.x;
    if (i < N_NODES) g_count[i] = 0;
}

__global__ void k_extract_count(const int* __restrict__ ei_w) {
    int e = blockIdx.x * blockDim.x + threadIdx.x;
    if (e >= N_EDGES) return;
    int s, d;
    if (g_is64) {
        s = ei_w[2 * (size_t)e];
        d = ei_w[2 * ((size_t)N_EDGES + e)];
    } else {
        s = ei_w[e];
        d = ei_w[N_EDGES + e];
    }
    s = clampN(s); d = clampN(d);
    g_srcs[e] = s;
    g_dsts[e] = d;
    atomicAdd(&g_count[d], 1);
}

// ---------------- 3-phase decoupled scan ----------------
__global__ void k_scan_phase1() {
    __shared__ int sm[1024];
    const int b = blockIdx.x, t = threadIdx.x;
    const int idx = b * SCAN_CHUNK + t;
    int v = (t < SCAN_CHUNK) ? g_count[idx] : 0;
    sm[t] = v;
    __syncthreads();
    for (int off = 1; off < 1024; off <<= 1) {
        int u = (t >= off) ? sm[t - off] : 0;
        __syncthreads();
        sm[t] += u;
        __syncthreads();
    }
    if (t < SCAN_CHUNK) g_rowstart[idx] = sm[t] - v;
    if (t == 1023) g_blocksum[b] = sm[1023];
}

__global__ void k_scan_phase2() {
    if (threadIdx.x == 0) {
        int run = 0;
        for (int i = 0; i < SCAN_BLOCKS; i++) {
            g_blockoff[i] = run;
            run += g_blocksum[i];
        }
        g_rowstart[N_NODES] = run;
    }
}

__global__ void k_scan_phase3() {
    const int b = blockIdx.x, t = threadIdx.x;
    if (t < SCAN_CHUNK) {
        int idx = b * SCAN_CHUNK + t;
        int rs = g_rowstart[idx] + g_blockoff[b];
        g_rowstart[idx] = rs;
        g_cursor[idx]   = rs;
    }
}

__global__ void k_fill_src() {
    int e = blockIdx.x * blockDim.x + threadIdx.x;
    if (e < N_EDGES) {
        int pos = atomicAdd(&g_cursor[g_dsts[e]], 1);
        g_src[pos] = g_srcs[e];
    }
}

// ---------------- one-time tf32 pre-rounding ----------------
__global__ void k_round_x(const float* __restrict__ src) {
    int i = blockIdx.x * blockDim.x + threadIdx.x;
    if (i < N_NODES * IN_DIM) g_xr[i] = roundtf(src[i]);
}

__global__ void k_round_weights(const float* __restrict__ Wl1, const float* __restrict__ Wr1,
                                const float* __restrict__ Wl2, const float* __restrict__ Wr2,
                                const float* __restrict__ Wl3, const float* __restrict__ Wr3) {
    int i = blockIdx.x * blockDim.x + threadIdx.x;
    if (i >= W_TOTAL) return;
    float v;
    if      (i < WO_R1) v = Wl1[i - WO_L1];
    else if (i < WO_L2) v = Wr1[i - WO_R1];
    else if (i < WO_R2) v = Wl2[i - WO_L2];
    else if (i < WO_L3) v = Wr2[i - WO_R2];
    else if (i < WO_R3) v = Wl3[i - WO_L3];
    else                v = Wr3[i - WO_R3];
    g_wr[i] = roundtf(v);
}

// ---------------- mean aggregation over in-edges (tf32-rounded output) -------
template <int D>
__global__ void k_aggregate(const float* __restrict__ x, float* __restrict__ out) {
    constexpr int TPN = D / 4;
    constexpr int NPB = 256 / TPN;
    int node = blockIdx.x * NPB + threadIdx.x / TPN;
    int lane = threadIdx.x % TPN;
    if (node >= N_NODES) return;

    const int beg = g_rowstart[node];
    const int end = g_rowstart[node + 1];
    const float4* xv = (const float4*)x;

    float ax = 0.f, ay = 0.f, az = 0.f, aw = 0.f;
    int j = beg;
    for (; j + 4 <= end; j += 4) {
        int s0 = g_src[j + 0], s1 = g_src[j + 1], s2 = g_src[j + 2], s3 = g_src[j + 3];
        float4 v0 = xv[(size_t)s0 * TPN + lane];
        float4 v1 = xv[(size_t)s1 * TPN + lane];
        float4 v2 = xv[(size_t)s2 * TPN + lane];
        float4 v3 = xv[(size_t)s3 * TPN + lane];
        ax += v0.x + v1.x + v2.x + v3.x;
        ay += v0.y + v1.y + v2.y + v3.y;
        az += v0.z + v1.z + v2.z + v3.z;
        aw += v0.w + v1.w + v2.w + v3.w;
    }
    for (; j < end; j++) {
        float4 v = xv[(size_t)g_src[j] * TPN + lane];
        ax += v.x; ay += v.y; az += v.z; aw += v.w;
    }
    float inv = (end > beg) ? 1.f / (float)(end - beg) : 0.f;
    float4 r = make_float4(roundtf(ax * inv), roundtf(ay * inv),
                           roundtf(az * inv), roundtf(aw * inv));
    ((float4*)out)[(size_t)node * TPN + lane] = r;
}

// ---------------- tf32 tensor-core single-source GEMM (half layer) ----------
// mode 0 (Wr): C = A@W^T + bias                 (no relu, no round)
// mode 1 (Wl): C = A@W^T + R  (+relu+round if relu_round)
// BM=128, BN=64, BK=32, 256 thr (4M x 2N warps), cp.async double-buffered.
__device__ __forceinline__ void mma_tf32(float* c,
                                         uint32_t a0, uint32_t a1, uint32_t a2, uint32_t a3,
                                         uint32_t b0, uint32_t b1) {
    asm volatile(
        "mma.sync.aligned.m16n8k8.row.col.f32.tf32.tf32.f32 "
        "{%0,%1,%2,%3}, {%4,%5,%6,%7}, {%8,%9}, {%0,%1,%2,%3};"
        : "+f"(c[0]), "+f"(c[1]), "+f"(c[2]), "+f"(c[3])
        : "r"(a0), "r"(a1), "r"(a2), "r"(a3), "r"(b0), "r"(b1));
}

#define GEMM_LDS    36
#define GEMM_TILE_A (128 * GEMM_LDS)
#define GEMM_TILE_B (64 * GEMM_LDS)
#define GEMM_BOFF   (2 * GEMM_TILE_A)
#define GEMM_SMEM   ((2 * GEMM_TILE_A + 2 * GEMM_TILE_B) * 4)   // 55296 B

__global__ __launch_bounds__(256, 4)
void k_gemm_half(const float* __restrict__ A, const float* __restrict__ W,
                 int K, const float* __restrict__ bias,
                 const float* __restrict__ R,
                 float* __restrict__ C, int mode, int relu_round) {
    extern __shared__ uint32_t smbuf[];

    const int t    = threadIdx.x;
    const int warp = t >> 5, lane = t & 31;
    const int g    = lane >> 2, tg = lane & 3;
    const int wm   = warp & 3;
    const int wn   = warp >> 2;
    const int row0 = blockIdx.x * 128;
    const int col0 = blockIdx.y * 64;

    const int lr = t >> 3;
    const int kq = t & 7;

    const int nTiles = K >> 5;

    float acc[2][4][4] = {};

    auto issue = [&](int tile) {
        const int s = tile & 1;
        const int kt = tile << 5;
        #pragma unroll
        for (int i = 0; i < 4; i++) {
            int row = lr + 32 * i;
            uint32_t da = (uint32_t)__cvta_generic_to_shared(
                &smbuf[s * GEMM_TILE_A + row * GEMM_LDS + kq * 4]);
            const float* ga = &A[(size_t)(row0 + row) * K + kt + kq * 4];
            int sz = (row0 + row < N_NODES) ? 16 : 0;
            asm volatile("cp.async.cg.shared.global [%0], [%1], 16, %2;"
                         :: "r"(da), "l"(ga), "r"(sz));
        }
        #pragma unroll
        for (int i = 0; i < 2; i++) {
            int row = lr + 32 * i;
            uint32_t db = (uint32_t)__cvta_generic_to_shared(
                &smbuf[GEMM_BOFF + s * GEMM_TILE_B + row * GEMM_LDS + kq * 4]);
            const float* gw = &W[(size_t)(col0 + row) * K + kt + kq * 4];
            asm volatile("cp.async.cg.shared.global [%0], [%1], 16;"
                         :: "r"(db), "l"(gw));
        }
        asm volatile("cp.async.commit_group;");
    };

    issue(0);
    for (int tile = 0; tile < nTiles; ++tile) {
        if (tile + 1 < nTiles) {
            issue(tile + 1);
            asm volatile("cp.async.wait_group 1;");
        } else {
            asm volatile("cp.async.wait_group 0;");
        }
        __syncthreads();

        const uint32_t* Asb = &smbuf[(tile & 1) * GEMM_TILE_A];
        const uint32_t* Bsb = &smbuf[GEMM_BOFF + (tile & 1) * GEMM_TILE_B];

        #pragma unroll
        for (int kk = 0; kk < 32; kk += 8) {
            uint32_t bf[4][2];
            #pragma unroll
            for (int nt = 0; nt < 4; nt++) {
                int n = wn * 32 + nt * 8 + g;
                bf[nt][0] = Bsb[n * GEMM_LDS + kk + tg];
                bf[nt][1] = Bsb[n * GEMM_LDS + kk + tg + 4];
            }
            #pragma unroll
            for (int mt = 0; mt < 2; mt++) {
                int r = wm * 32 + mt * 16 + g;
                uint32_t a0 = Asb[(r    ) * GEMM_LDS + kk + tg];
                uint32_t a1 = Asb[(r + 8) * GEMM_LDS + kk + tg];
                uint32_t a2 = Asb[(r    ) * GEMM_LDS + kk + tg + 4];
                uint32_t a3 = Asb[(r + 8) * GEMM_LDS + kk + tg + 4];
                #pragma unroll
                for (int nt = 0; nt < 4; nt++)
                    mma_tf32(acc[mt][nt], a0, a1, a2, a3, bf[nt][0], bf[nt][1]);
            }
        }
        __syncthreads();
    }

    #pragma unroll
    for (int mt = 0; mt < 2; mt++) {
        int r = row0 + wm * 32 + mt * 16 + g;
        #pragma unroll
        for (int nt = 0; nt < 4; nt++) {
            int col = col0 + wn * 32 + nt * 8 + tg * 2;
            float a0 = acc[mt][nt][0], a1 = acc[mt][nt][1];
            float a2 = acc[mt][nt][2], a3 = acc[mt][nt][3];
            if (mode == 0) {
                float2 bv = *(const float2*)&bias[col];
                a0 += bv.x; a1 += bv.y; a2 += bv.x; a3 += bv.y;
            } else {
                if (r < N_NODES) {
                    float2 r0 = *(const float2*)&R[(size_t)r * HID + col];
                    a0 += r0.x; a1 += r0.y;
                }
                if (r + 8 < N_NODES) {
                    float2 r1 = *(const float2*)&R[(size_t)(r + 8) * HID + col];
                    a2 += r1.x; a3 += r1.y;
                }
                if (relu_round) {
                    a0 = roundtf(fmaxf(a0, 0.f)); a1 = roundtf(fmaxf(a1, 0.f));
                    a2 = roundtf(fmaxf(a2, 0.f)); a3 = roundtf(fmaxf(a3, 0.f));
                }
            }
            if (r < N_NODES)     *(float2*)&C[(size_t)r * HID + col]       = make_float2(a0, a1);
            if (r + 8 < N_NODES) *(float2*)&C[(size_t)(r + 8) * HID + col] = make_float2(a2, a3);
        }
    }
}

// ---------------- launch ----------------
extern "C" void kernel_launch(void* const* d_in, const int* in_sizes, int n_in,
                              void* d_out, int out_size) {
    const float* x   = (const float*)d_in[0];
    const int*   eiw = (const int*)d_in[1];
    const float* Wl1 = (const float*)d_in[2];
    const float* Wr1 = (const float*)d_in[3];
    const float* b1  = (const float*)d_in[4];
    const float* Wl2 = (const float*)d_in[5];
    const float* Wr2 = (const float*)d_in[6];
    const float* b2  = (const float*)d_in[7];
    const float* Wl3 = (const float*)d_in[8];
    const float* Wr3 = (const float*)d_in[9];
    const float* b3  = (const float*)d_in[10];
    float*       out = (float*)d_out;

    float *agg, *h, *h2, *R, *xr, *wr;
    cudaGetSymbolAddress((void**)&agg, g_agg);
    cudaGetSymbolAddress((void**)&h,   g_h);
    cudaGetSymbolAddress((void**)&h2,  g_h2);
    cudaGetSymbolAddress((void**)&R,   g_R);
    cudaGetSymbolAddress((void**)&xr,  g_xr);
    cudaGetSymbolAddress((void**)&wr,  g_wr);

    cudaFuncSetAttribute(k_gemm_half,
                         cudaFuncAttributeMaxDynamicSharedMemorySize, GEMM_SMEM);

    // side stream + fork/join events (created per call; host-side only,
    // never destroyed — kernel_launch runs at most a handful of times)
    cudaStream_t side;
    cudaStreamCreateWithFlags(&side, cudaStreamNonBlocking);
    cudaEvent_t evF0, evJ1, evF2, evJ2, evF3, evJ3;
    cudaEventCreateWithFlags(&evF0, cudaEventDisableTiming);
    cudaEventCreateWithFlags(&evJ1, cudaEventDisableTiming);
    cudaEventCreateWithFlags(&evF2, cudaEventDisableTiming);
    cudaEventCreateWithFlags(&evJ2, cudaEventDisableTiming);
    cudaEventCreateWithFlags(&evF3, cudaEventDisableTiming);
    cudaEventCreateWithFlags(&evJ3, cudaEventDisableTiming);

    dim3 ggrid((N_NODES + 127) / 128, HID / 64);    // 313 x 4

    // ---- fork 0: side does rounding + Wr1 while main builds CSR + agg1 ----
    cudaEventRecord(evF0, 0);
    cudaStreamWaitEvent(side, evF0, 0);

    // side chain: pre-rounding -> R1 = xr@Wr1^T + b1
    k_round_x<<<(N_NODES * IN_DIM + 255) / 256, 256, 0, side>>>(x);
    k_round_weights<<<(W_TOTAL + 255) / 256, 256, 0, side>>>(Wl1, Wr1, Wl2, Wr2, Wl3, Wr3);
    k_gemm_half<<<ggrid, 256, GEMM_SMEM, side>>>(xr, wr + WO_R1, IN_DIM, b1, nullptr, R, 0, 0);
    cudaEventRecord(evJ1, side);

    // main chain: CSR build -> agg1
    k_zero_counts<<<(N_NODES + 255) / 256, 256>>>();
    k_detect<<<1, 256>>>(eiw);
    k_extract_count<<<(N_EDGES + 255) / 256, 256>>>(eiw);
    k_scan_phase1<<<SCAN_BLOCKS, 1024>>>();
    k_scan_phase2<<<1, 32>>>();
    k_scan_phase3<<<SCAN_BLOCKS, 1024>>>();
    k_fill_src<<<(N_EDGES + 255) / 256, 256>>>();
    k_aggregate<IN_DIM><<<(N_NODES + 7) / 8, 256>>>(x, agg);

    cudaStreamWaitEvent(0, evJ1, 0);
    // h = relu(agg@Wl1^T + R1), rounded
    k_gemm_half<<<ggrid, 256, GEMM_SMEM>>>(agg, wr + WO_L1, IN_DIM, nullptr, R, h, 1, 1);

    // ---- layer 2: fork agg2 || Wr2 ----
    cudaEventRecord(evF2, 0);
    cudaStreamWaitEvent(side, evF2, 0);
    k_gemm_half<<<ggrid, 256, GEMM_SMEM, side>>>(h, wr + WO_R2, HID, b2, nullptr, R, 0, 0);
    cudaEventRecord(evJ2, side);

    k_aggregate<HID><<<(N_NODES + 3) / 4, 256>>>(h, agg);
    cudaStreamWaitEvent(0, evJ2, 0);
    k_gemm_half<<<ggrid, 256, GEMM_SMEM>>>(agg, wr + WO_L2, HID, nullptr, R, h2, 1, 1);

    // ---- layer 3: fork agg3 || Wr3 ----
    cudaEventRecord(evF3, 0);
    cudaStreamWaitEvent(side, evF3, 0);
    k_gemm_half<<<ggrid, 256, GEMM_SMEM, side>>>(h2, wr + WO_R3, HID, b3, nullptr, R, 0, 0);
    cudaEventRecord(evJ3, side);

    k_aggregate<HID><<<(N_NODES + 3) / 4, 256>>>(h2, agg);
    cudaStreamWaitEvent(0, evJ3, 0);
    k_gemm_half<<<ggrid, 256, GEMM_SMEM>>>(agg, wr + WO_L3, HID, nullptr, R, out, 1, 0);
}

// round 10
// speedup vs baseline: 1.5413x; 1.5413x over previous
#include <cuda_runtime.h>
#include <cuda_fp16.h>
#include <cstdint>

#define N_NODES 40000
#define N_EDGES 640000
#define IN_DIM  128
#define HID     256

#define SCAN_BLOCKS 40
#define SCAN_CHUNK  1000   // 40 * 1000 = 40000 exactly

// ---------------- device scratch (static, no allocations) ----------------
__device__ int   g_is64;
__device__ int   g_srcs[N_EDGES];
__device__ int   g_dsts[N_EDGES];
__device__ int   g_count[N_NODES];
__device__ int   g_rowstart[N_NODES + 1];
__device__ int   g_cursor[N_NODES];
__device__ int   g_src[N_EDGES];
__device__ int   g_blocksum[SCAN_BLOCKS];
__device__ int   g_blockoff[SCAN_BLOCKS];

#define WO_L1 0
#define WO_R1 (HID * IN_DIM)
#define WO_L2 (2 * HID * IN_DIM)
#define WO_R2 (2 * HID * IN_DIM + HID * HID)
#define WO_L3 (2 * HID * IN_DIM + 2 * HID * HID)
#define WO_R3 (2 * HID * IN_DIM + 3 * HID * HID)
#define W_TOTAL (2 * HID * IN_DIM + 4 * HID * HID)

__device__ __align__(16) __half g_xh [(size_t)N_NODES * IN_DIM];
__device__ __align__(16) __half g_wh [W_TOTAL];
__device__ __align__(16) __half g_agg[(size_t)N_NODES * HID];
__device__ __align__(16) __half g_h  [(size_t)N_NODES * HID];
__device__ __align__(16) __half g_h2 [(size_t)N_NODES * HID];

// ---------------- edge-index dtype detection ----------------
__global__ void k_detect(const int* __restrict__ ei_w) {
    __shared__ int acc;
    if (threadIdx.x == 0) acc = 0;
    __syncthreads();
    int v = 0;
    for (int i = threadIdx.x; i < 2048; i += 256) v |= ei_w[2 * i + 1];
    atomicOr(&acc, v);
    __syncthreads();
    if (threadIdx.x == 0) g_is64 = (acc == 0) ? 1 : 0;
}

__device__ __forceinline__ int clampN(int v) {
    return v < 0 ? 0 : (v >= N_NODES ? N_NODES - 1 : v);
}

__global__ void k_zero_counts() {
    int i = blockIdx.x * blockDim.x + threadIdx.x;
    if (i < N_NODES) g_count[i] = 0;
}

__global__ void k_extract_count(const int* __restrict__ ei_w) {
    int e = blockIdx.x * blockDim.x + threadIdx.x;
    if (e >= N_EDGES) return;
    int s, d;
    if (g_is64) {
        s = ei_w[2 * (size_t)e];
        d = ei_w[2 * ((size_t)N_EDGES + e)];
    } else {
        s = ei_w[e];
        d = ei_w[N_EDGES + e];
    }
    s = clampN(s); d = clampN(d);
    g_srcs[e] = s;
    g_dsts[e] = d;
    atomicAdd(&g_count[d], 1);
}

// ---------------- 3-phase decoupled scan ----------------
__global__ void k_scan_phase1() {
    __shared__ int sm[1024];
    const int b = blockIdx.x, t = threadIdx.x;
    const int idx = b * SCAN_CHUNK + t;
    int v = (t < SCAN_CHUNK) ? g_count[idx] : 0;
    sm[t] = v;
    __syncthreads();
    for (int off = 1; off < 1024; off <<= 1) {
        int u = (t >= off) ? sm[t - off] : 0;
        __syncthreads();
        sm[t] += u;
        __syncthreads();
    }
    if (t < SCAN_CHUNK) g_rowstart[idx] = sm[t] - v;
    if (t == 1023) g_blocksum[b] = sm[1023];
}

__global__ void k_scan_phase2() {
    if (threadIdx.x == 0) {
        int run = 0;
        for (int i = 0; i < SCAN_BLOCKS; i++) {
            g_blockoff[i] = run;
            run += g_blocksum[i];
        }
        g_rowstart[N_NODES] = run;
    }
}

__global__ void k_scan_phase3() {
    const int b = blockIdx.x, t = threadIdx.x;
    if (t < SCAN_CHUNK) {
        int idx = b * SCAN_CHUNK + t;
        int rs = g_rowstart[idx] + g_blockoff[b];
        g_rowstart[idx] = rs;
        g_cursor[idx]   = rs;
    }
}

__global__ void k_fill_src() {
    int e = blockIdx.x * blockDim.x + threadIdx.x;
    if (e < N_EDGES) {
        int pos = atomicAdd(&g_cursor[g_dsts[e]], 1);
        g_src[pos] = g_srcs[e];
    }
}

// ---------------- fp32 -> fp16 conversion (one-time) ----------------
__global__ void k_half_x(const float* __restrict__ src) {
    int i = blockIdx.x * blockDim.x + threadIdx.x;
    if (i < N_NODES * IN_DIM) g_xh[i] = __float2half_rn(src[i]);
}

__global__ void k_half_w(const float* __restrict__ Wl1, const float* __restrict__ Wr1,
                         const float* __restrict__ Wl2, const float* __restrict__ Wr2,
                         const float* __restrict__ Wl3, const float* __restrict__ Wr3) {
    int i = blockIdx.x * blockDim.x + threadIdx.x;
    if (i >= W_TOTAL) return;
    float v;
    if      (i < WO_R1) v = Wl1[i - WO_L1];
    else if (i < WO_L2) v = Wr1[i - WO_R1];
    else if (i < WO_R2) v = Wl2[i - WO_L2];
    else if (i < WO_L3) v = Wr2[i - WO_R2];
    else if (i < WO_R3) v = Wl3[i - WO_L3];
    else                v = Wr3[i - WO_R3];
    g_wh[i] = __float2half_rn(v);
}

// ---------------- mean aggregation over in-edges (fp16 in/out, fp32 acc) ----
template <int D>
__global__ void k_aggregate_h(const __half* __restrict__ x, __half* __restrict__ out) {
    constexpr int TPN = D / 8;        // threads per node, uint4 = 8 halves
    constexpr int NPB = 256 / TPN;
    int node = blockIdx.x * NPB + threadIdx.x / TPN;
    int lane = threadIdx.x % TPN;
    if (node >= N_NODES) return;

    const int beg = g_rowstart[node];
    const int end = g_rowstart[node + 1];
    const uint4* xv = (const uint4*)x;

    float acc[8] = {};
    int j = beg;
    for (; j + 4 <= end; j += 4) {
        int s0 = g_src[j + 0], s1 = g_src[j + 1], s2 = g_src[j + 2], s3 = g_src[j + 3];
        uint4 v0 = xv[(size_t)s0 * TPN + lane];
        uint4 v1 = xv[(size_t)s1 * TPN + lane];
        uint4 v2 = xv[(size_t)s2 * TPN + lane];
        uint4 v3 = xv[(size_t)s3 * TPN + lane];
        #pragma unroll
        for (int q = 0; q < 4; q++) {
            uint32_t w0 = (&v0.x)[q], w1 = (&v1.x)[q], w2 = (&v2.x)[q], w3 = (&v3.x)[q];
            float2 f0 = __half22float2(*(__half2*)&w0);
            float2 f1 = __half22float2(*(__half2*)&w1);
            float2 f2 = __half22float2(*(__half2*)&w2);
            float2 f3 = __half22float2(*(__half2*)&w3);
            acc[2 * q + 0] += f0.x + f1.x + f2.x + f3.x;
            acc[2 * q + 1] += f0.y + f1.y + f2.y + f3.y;
        }
    }
    for (; j < end; j++) {
        uint4 v = xv[(size_t)g_src[j] * TPN + lane];
        #pragma unroll
        for (int q = 0; q < 4; q++) {
            uint32_t w = (&v.x)[q];
            float2 f = __half22float2(*(__half2*)&w);
            acc[2 * q + 0] += f.x;
            acc[2 * q + 1] += f.y;
        }
    }
    float inv = (end > beg) ? 1.f / (float)(end - beg) : 0.f;
    uint4 r;
    #pragma unroll
    for (int q = 0; q < 4; q++) {
        __half2 hp = __floats2half2_rn(acc[2 * q] * inv, acc[2 * q + 1] * inv);
        (&r.x)[q] = *(uint32_t*)&hp;
    }
    ((uint4*)out)[(size_t)node * TPN + lane] = r;
}

// ---------------- fp16 tensor-core fused dual-source GEMM --------------------
// C[M,256] = A0@W0^T + A1@W1^T + b (optional ReLU); fp32 accumulate.
// BM=BN=128, BK=32 halves (2 k16-steps), 256 thr (4M x 2N warps), warp 32x64.
// cp.async double-buffered. smem stride 40 halves (80 B) -> conflict-free frags.
__device__ __forceinline__ void mma_f16(float* c,
                                        uint32_t a0, uint32_t a1, uint32_t a2, uint32_t a3,
                                        uint32_t b0, uint32_t b1) {
    asm volatile(
        "mma.sync.aligned.m16n8k16.row.col.f32.f16.f16.f32 "
        "{%0,%1,%2,%3}, {%4,%5,%6,%7}, {%8,%9}, {%0,%1,%2,%3};"
        : "+f"(c[0]), "+f"(c[1]), "+f"(c[2]), "+f"(c[3])
        : "r"(a0), "r"(a1), "r"(a2), "r"(a3), "r"(b0), "r"(b1));
}

#define GLDS  40                       // halves per smem row (80 B)
#define GTILE (128 * GLDS)             // halves per stage buffer
#define GSMEM (4 * GTILE * 2)          // bytes: [As0|As1|Bs0|Bs1] = 40960

__global__ __launch_bounds__(256, 2)
void k_gemm_h(const __half* __restrict__ A0, const __half* __restrict__ W0,
              const __half* __restrict__ A1, const __half* __restrict__ W1,
              int K, const float* __restrict__ bias,
              void* __restrict__ Cout, int relu_half) {
    extern __shared__ __half smh[];

    const int t    = threadIdx.x;
    const int warp = t >> 5, lane = t & 31;
    const int g    = lane >> 2, tg = lane & 3;
    const int wm   = warp & 3;                 // M offset 32*wm
    const int wn   = warp >> 2;                // N offset 64*wn
    const int row0 = blockIdx.x * 128;
    const int col0 = blockIdx.y * 128;

    const int lr = t >> 2;                     // 0..63 load row (2 passes)
    const int kq = t & 3;                      // 0..3, 16B (8-half) chunk

    const int tilesPerSrc = K >> 5;
    const int nTiles = 2 * tilesPerSrc;

    float acc[2][8][4] = {};

    auto issue = [&](int tile) {
        const int s = tile & 1;
        const __half* A = (tile < tilesPerSrc) ? A0 : A1;
        const __half* W = (tile < tilesPerSrc) ? W0 : W1;
        const int kt = ((tile < tilesPerSrc) ? tile : tile - tilesPerSrc) << 5;
        #pragma unroll
        for (int p = 0; p < 2; p++) {
            int row = lr + 64 * p;
            uint32_t da = (uint32_t)__cvta_generic_to_shared(
                &smh[s * GTILE + row * GLDS + kq * 8]);
            const __half* ga = &A[(size_t)(row0 + row) * K + kt + kq * 8];
            int sz = (row0 + row < N_NODES) ? 16 : 0;
            asm volatile("cp.async.cg.shared.global [%0], [%1], 16, %2;"
                         :: "r"(da), "l"(ga), "r"(sz));
            uint32_t db = (uint32_t)__cvta_generic_to_shared(
                &smh[2 * GTILE + s * GTILE + row * GLDS + kq * 8]);
            const __half* gw = &W[(size_t)(col0 + row) * K + kt + kq * 8];
            asm volatile("cp.async.cg.shared.global [%0], [%1], 16;"
                         :: "r"(db), "l"(gw));
        }
        asm volatile("cp.async.commit_group;");
    };

    issue(0);
    for (int tile = 0; tile < nTiles; ++tile) {
        if (tile + 1 < nTiles) {
            issue(tile + 1);
            asm volatile("cp.async.wait_group 1;");
        } else {
            asm volatile("cp.async.wait_group 0;");
        }
        __syncthreads();

        const __half* Asb = &smh[(tile & 1) * GTILE];
        const __half* Bsb = &smh[2 * GTILE + (tile & 1) * GTILE];

        #pragma unroll
        for (int kk = 0; kk < 32; kk += 16) {
            uint32_t bf[8][2];
            #pragma unroll
            for (int nt = 0; nt < 8; nt++) {
                int n = wn * 64 + nt * 8 + g;
                bf[nt][0] = *(const uint32_t*)&Bsb[n * GLDS + kk + 2 * tg];
                bf[nt][1] = *(const uint32_t*)&Bsb[n * GLDS + kk + 2 * tg + 8];
            }
            #pragma unroll
            for (int mt = 0; mt < 2; mt++) {
                int r = wm * 32 + mt * 16 + g;
                uint32_t a0 = *(const uint32_t*)&Asb[(r    ) * GLDS + kk + 2 * tg];
                uint32_t a1 = *(const uint32_t*)&Asb[(r + 8) * GLDS + kk + 2 * tg];
                uint32_t a2 = *(const uint32_t*)&Asb[(r    ) * GLDS + kk + 2 * tg + 8];
                uint32_t a3 = *(const uint32_t*)&Asb[(r + 8) * GLDS + kk + 2 * tg + 8];
                #pragma unroll
                for (int nt = 0; nt < 8; nt++)
                    mma_f16(acc[mt][nt], a0, a1, a2, a3, bf[nt][0], bf[nt][1]);
            }
        }
        __syncthreads();
    }

    // epilogue: bias; relu+fp16 store (layers 1-2) or fp32 store (layer 3)
    #pragma unroll
    for (int mt = 0; mt < 2; mt++) {
        int r = row0 + wm * 32 + mt * 16 + g;
        #pragma unroll
        for (int nt = 0; nt < 8; nt++) {
            int col = col0 + wn * 64 + nt * 8 + tg * 2;
            float2 bv = *(const float2*)&bias[col];
            float v0 = acc[mt][nt][0] + bv.x;
            float v1 = acc[mt][nt][1] + bv.y;
            float v2 = acc[mt][nt][2] + bv.x;
            float v3 = acc[mt][nt][3] + bv.y;
            if (relu_half) {
                __half* C = (__half*)Cout;
                __half2 h0 = __floats2half2_rn(fmaxf(v0, 0.f), fmaxf(v1, 0.f));
                __half2 h1 = __floats2half2_rn(fmaxf(v2, 0.f), fmaxf(v3, 0.f));
                if (r < N_NODES)     *(__half2*)&C[(size_t)r * HID + col]       = h0;
                if (r + 8 < N_NODES) *(__half2*)&C[(size_t)(r + 8) * HID + col] = h1;
            } else {
                float* C = (float*)Cout;
                if (r < N_NODES)     *(float2*)&C[(size_t)r * HID + col]       = make_float2(v0, v1);
                if (r + 8 < N_NODES) *(float2*)&C[(size_t)(r + 8) * HID + col] = make_float2(v2, v3);
            }
        }
    }
}

// ---------------- launch ----------------
extern "C" void kernel_launch(void* const* d_in, const int* in_sizes, int n_in,
                              void* d_out, int out_size) {
    const float* x   = (const float*)d_in[0];
    const int*   eiw = (const int*)d_in[1];
    const float* Wl1 = (const float*)d_in[2];
    const float* Wr1 = (const float*)d_in[3];
    const float* b1  = (const float*)d_in[4];
    const float* Wl2 = (const float*)d_in[5];
    const float* Wr2 = (const float*)d_in[6];
    const float* b2  = (const float*)d_in[7];
    const float* Wl3 = (const float*)d_in[8];
    const float* Wr3 = (const float*)d_in[9];
    const float* b3  = (const float*)d_in[10];
    float*       out = (float*)d_out;

    __half *agg, *h, *h2, *xh, *wh;
    cudaGetSymbolAddress((void**)&agg, g_agg);
    cudaGetSymbolAddress((void**)&h,   g_h);
    cudaGetSymbolAddress((void**)&h2,  g_h2);
    cudaGetSymbolAddress((void**)&xh,  g_xh);
    cudaGetSymbolAddress((void**)&wh,  g_wh);

    cudaFuncSetAttribute(k_gemm_h,
                         cudaFuncAttributeMaxDynamicSharedMemorySize, GSMEM);

    // CSR build
    k_zero_counts<<<(N_NODES + 255) / 256, 256>>>();
    k_detect<<<1, 256>>>(eiw);
    k_extract_count<<<(N_EDGES + 255) / 256, 256>>>(eiw);
    k_scan_phase1<<<SCAN_BLOCKS, 1024>>>();
    k_scan_phase2<<<1, 32>>>();
    k_scan_phase3<<<SCAN_BLOCKS, 1024>>>();
    k_fill_src<<<(N_EDGES + 255) / 256, 256>>>();

    // fp16 conversion of x and weights
    k_half_x<<<(N_NODES * IN_DIM + 255) / 256, 256>>>(x);
    k_half_w<<<(W_TOTAL + 255) / 256, 256>>>(Wl1, Wr1, Wl2, Wr2, Wl3, Wr3);

    dim3 ggrid((N_NODES + 127) / 128, HID / 128);   // 313 x 2

    // Layer 1: 128 -> 256, relu, fp16 out
    k_aggregate_h<IN_DIM><<<(N_NODES + 15) / 16, 256>>>(xh, agg);
    k_gemm_h<<<ggrid, 256, GSMEM>>>(agg, wh + WO_L1, xh, wh + WO_R1,
                                    IN_DIM, b1, h, 1);

    // Layer 2: 256 -> 256, relu, fp16 out
    k_aggregate_h<HID><<<(N_NODES + 7) / 8, 256>>>(h, agg);
    k_gemm_h<<<ggrid, 256, GSMEM>>>(agg, wh + WO_L2, h, wh + WO_R2,
                                    HID, b2, h2, 1);

    // Layer 3: 256 -> 256, fp32 out to d_out
    k_aggregate_h<HID><<<(N_NODES + 7) / 8, 256>>>(h2, agg);
    k_gemm_h<<<ggrid, 256, GSMEM>>>(agg, wh + WO_L3, h2, wh + WO_R3,
                                    HID, b3, out, 0);
}

// round 11
// speedup vs baseline: 1.6143x; 1.0474x over previous
#include <cuda_runtime.h>
#include <cuda_fp16.h>
#include <cstdint>

#define N_NODES 40000
#define N_EDGES 640000
#define IN_DIM  128
#define HID     256

#define SCAN_BLOCKS 40
#define SCAN_CHUNK  1000   // 40 * 1000 = 40000 exactly

// ---------------- device scratch (static, no allocations) ----------------
__device__ int   g_is64;
__device__ int   g_srcs[N_EDGES];
__device__ int   g_dsts[N_EDGES];
__device__ int   g_count[N_NODES];
__device__ int   g_rowstart[N_NODES + 1];
__device__ int   g_cursor[N_NODES];
__device__ int   g_src[N_EDGES];
__device__ int   g_blocksum[SCAN_BLOCKS];

#define WO_L1 0
#define WO_R1 (HID * IN_DIM)
#define WO_L2 (2 * HID * IN_DIM)
#define WO_R2 (2 * HID * IN_DIM + HID * HID)
#define WO_L3 (2 * HID * IN_DIM + 2 * HID * HID)
#define WO_R3 (2 * HID * IN_DIM + 3 * HID * HID)
#define W_TOTAL (2 * HID * IN_DIM + 4 * HID * HID)
#define NX (N_NODES * IN_DIM)

__device__ __align__(16) __half g_xh [(size_t)NX];
__device__ __align__(16) __half g_wh [W_TOTAL];
__device__ __align__(16) __half g_agg[(size_t)N_NODES * HID];
__device__ __align__(16) __half g_h  [(size_t)N_NODES * HID];
__device__ __align__(16) __half g_h2 [(size_t)N_NODES * HID];

// ---------------- init: zero counts + (block 0) dtype detection ----------
__global__ void k_init(const int* __restrict__ ei_w) {
    int i = blockIdx.x * blockDim.x + threadIdx.x;
    if (i < N_NODES) g_count[i] = 0;
    if (blockIdx.x == 0) {
        __shared__ int acc;
        if (threadIdx.x == 0) acc = 0;
        __syncthreads();
        int v = 0;
        for (int j = threadIdx.x; j < 2048; j += 256) v |= ei_w[2 * j + 1];
        atomicOr(&acc, v);
        __syncthreads();
        if (threadIdx.x == 0) g_is64 = (acc == 0) ? 1 : 0;
    }
}

__device__ __forceinline__ int clampN(int v) {
    return v < 0 ? 0 : (v >= N_NODES ? N_NODES - 1 : v);
}

__global__ void k_extract_count(const int* __restrict__ ei_w) {
    int e = blockIdx.x * blockDim.x + threadIdx.x;
    if (e >= N_EDGES) return;
    int s, d;
    if (g_is64) {
        s = ei_w[2 * (size_t)e];
        d = ei_w[2 * ((size_t)N_EDGES + e)];
    } else {
        s = ei_w[e];
        d = ei_w[N_EDGES + e];
    }
    s = clampN(s); d = clampN(d);
    g_srcs[e] = s;
    g_dsts[e] = d;
    atomicAdd(&g_count[d], 1);
}

// ---------------- decoupled scan (phase1 + fused phase2/3) ----------------
__global__ void k_scan_phase1() {
    __shared__ int sm[1024];
    const int b = blockIdx.x, t = threadIdx.x;
    const int idx = b * SCAN_CHUNK + t;
    int v = (t < SCAN_CHUNK) ? g_count[idx] : 0;
    sm[t] = v;
    __syncthreads();
    for (int off = 1; off < 1024; off <<= 1) {
        int u = (t >= off) ? sm[t - off] : 0;
        __syncthreads();
        sm[t] += u;
        __syncthreads();
    }
    if (t < SCAN_CHUNK) g_rowstart[idx] = sm[t] - v;
    if (t == 1023) g_blocksum[b] = sm[1023];
}

__global__ void k_scan_phase23() {
    __shared__ int off_total[2];
    const int b = blockIdx.x, t = threadIdx.x;
    if (t == 0) {
        int run = 0;
        for (int i = 0; i < SCAN_BLOCKS; i++) {
            if (i == b) off_total[0] = run;
            run += g_blocksum[i];
        }
        off_total[1] = run;
    }
    __syncthreads();
    if (t < SCAN_CHUNK) {
        int idx = b * SCAN_CHUNK + t;
        int rs = g_rowstart[idx] + off_total[0];
        g_rowstart[idx] = rs;
        g_cursor[idx]   = rs;
    }
    if (b == 0 && t == 0) g_rowstart[N_NODES] = off_total[1];
}

__global__ void k_fill_src() {
    int e = blockIdx.x * blockDim.x + threadIdx.x;
    if (e < N_EDGES) {
        int pos = atomicAdd(&g_cursor[g_dsts[e]], 1);
        g_src[pos] = g_srcs[e];
    }
}

// ---------------- fused fp32 -> fp16 conversion of x + all weights ----------
__global__ void k_convert(const float* __restrict__ x,
                          const float* __restrict__ Wl1, const float* __restrict__ Wr1,
                          const float* __restrict__ Wl2, const float* __restrict__ Wr2,
                          const float* __restrict__ Wl3, const float* __restrict__ Wr3) {
    int i = blockIdx.x * blockDim.x + threadIdx.x;
    if (i < NX) {
        g_xh[i] = __float2half_rn(x[i]);
        return;
    }
    int j = i - NX;
    if (j >= W_TOTAL) return;
    float v;
    if      (j < WO_R1) v = Wl1[j - WO_L1];
    else if (j < WO_L2) v = Wr1[j - WO_R1];
    else if (j < WO_R2) v = Wl2[j - WO_L2];
    else if (j < WO_L3) v = Wr2[j - WO_R2];
    else if (j < WO_R3) v = Wl3[j - WO_L3];
    else                v = Wr3[j - WO_R3];
    g_wh[j] = __float2half_rn(v);
}

// ---------------- mean aggregation over in-edges (fp16 in/out, fp32 acc) ----
template <int D>
__global__ void k_aggregate_h(const __half* __restrict__ x, __half* __restrict__ out) {
    constexpr int TPN = D / 8;        // threads per node, uint4 = 8 halves
    constexpr int NPB = 256 / TPN;
    int node = blockIdx.x * NPB + threadIdx.x / TPN;
    int lane = threadIdx.x % TPN;
    if (node >= N_NODES) return;

    const int beg = g_rowstart[node];
    const int end = g_rowstart[node + 1];
    const uint4* xv = (const uint4*)x;

    float acc[8] = {};
    int j = beg;
    for (; j + 4 <= end; j += 4) {
        int s0 = g_src[j + 0], s1 = g_src[j + 1], s2 = g_src[j + 2], s3 = g_src[j + 3];
        uint4 v0 = xv[(size_t)s0 * TPN + lane];
        uint4 v1 = xv[(size_t)s1 * TPN + lane];
        uint4 v2 = xv[(size_t)s2 * TPN + lane];
        uint4 v3 = xv[(size_t)s3 * TPN + lane];
        #pragma unroll
        for (int q = 0; q < 4; q++) {
            uint32_t w0 = (&v0.x)[q], w1 = (&v1.x)[q], w2 = (&v2.x)[q], w3 = (&v3.x)[q];
            float2 f0 = __half22float2(*(__half2*)&w0);
            float2 f1 = __half22float2(*(__half2*)&w1);
            float2 f2 = __half22float2(*(__half2*)&w2);
            float2 f3 = __half22float2(*(__half2*)&w3);
            acc[2 * q + 0] += f0.x + f1.x + f2.x + f3.x;
            acc[2 * q + 1] += f0.y + f1.y + f2.y + f3.y;
        }
    }
    for (; j < end; j++) {
        uint4 v = xv[(size_t)g_src[j] * TPN + lane];
        #pragma unroll
        for (int q = 0; q < 4; q++) {
            uint32_t w = (&v.x)[q];
            float2 f = __half22float2(*(__half2*)&w);
            acc[2 * q + 0] += f.x;
            acc[2 * q + 1] += f.y;
        }
    }
    float inv = (end > beg) ? 1.f / (float)(end - beg) : 0.f;
    uint4 r;
    #pragma unroll
    for (int q = 0; q < 4; q++) {
        __half2 hp = __floats2half2_rn(acc[2 * q] * inv, acc[2 * q + 1] * inv);
        (&r.x)[q] = *(uint32_t*)&hp;
    }
    ((uint4*)out)[(size_t)node * TPN + lane] = r;
}

// ---------------- fp16 tensor-core fused dual-source GEMM --------------------
// C[M,256] = A0@W0^T + A1@W1^T + b (optional ReLU); fp32 accumulate.
// BM=BN=128, BK=32 halves; 4-stage cp.async, issue distance 2, ONE barrier/tile
// (writer of buffer (t+2)%4 can at worst race a reader of (t-1)%4 — distinct).
__device__ __forceinline__ void mma_f16(float* c,
                                        uint32_t a0, uint32_t a1, uint32_t a2, uint32_t a3,
                                        uint32_t b0, uint32_t b1) {
    asm volatile(
        "mma.sync.aligned.m16n8k16.row.col.f32.f16.f16.f32 "
        "{%0,%1,%2,%3}, {%4,%5,%6,%7}, {%8,%9}, {%0,%1,%2,%3};"
        : "+f"(c[0]), "+f"(c[1]), "+f"(c[2]), "+f"(c[3])
        : "r"(a0), "r"(a1), "r"(a2), "r"(a3), "r"(b0), "r"(b1));
}

#define GLDS  40                       // halves per smem row (80 B)
#define GTILE (128 * GLDS)             // halves per stage buffer (10 KB)
#define GSMEM (8 * GTILE * 2)          // 4 A stages + 4 B stages = 81920 B

__global__ __launch_bounds__(256, 2)
void k_gemm_h(const __half* __restrict__ A0, const __half* __restrict__ W0,
              const __half* __restrict__ A1, const __half* __restrict__ W1,
              int K, const float* __restrict__ bias,
              void* __restrict__ Cout, int relu_half) {
    extern __shared__ __half smh[];    // [As0..As3 | Bs0..Bs3]

    const int t    = threadIdx.x;
    const int warp = t >> 5, lane = t & 31;
    const int g    = lane >> 2, tg = lane & 3;
    const int wm   = warp & 3;                 // M offset 32*wm
    const int wn   = warp >> 2;                // N offset 64*wn
    const int row0 = blockIdx.x * 128;
    const int col0 = blockIdx.y * 128;

    const int lr = t >> 2;                     // 0..63 load row (2 passes)
    const int kq = t & 3;                      // 0..3, 16B (8-half) chunk

    const int tilesPerSrc = K >> 5;
    const int nTiles = 2 * tilesPerSrc;

    float acc[2][8][4] = {};

    auto issue = [&](int tile) {
        const int s = tile & 3;
        const __half* A = (tile < tilesPerSrc) ? A0 : A1;
        const __half* W = (tile < tilesPerSrc) ? W0 : W1;
        const int kt = ((tile < tilesPerSrc) ? tile : tile - tilesPerSrc) << 5;
        #pragma unroll
        for (int p = 0; p < 2; p++) {
            int row = lr + 64 * p;
            uint32_t da = (uint32_t)__cvta_generic_to_shared(
                &smh[s * GTILE + row * GLDS + kq * 8]);
            const __half* ga = &A[(size_t)(row0 + row) * K + kt + kq * 8];
            int sz = (row0 + row < N_NODES) ? 16 : 0;
            asm volatile("cp.async.cg.shared.global [%0], [%1], 16, %2;"
                         :: "r"(da), "l"(ga), "r"(sz));
            uint32_t db = (uint32_t)__cvta_generic_to_shared(
                &smh[4 * GTILE + s * GTILE + row * GLDS + kq * 8]);
            const __half* gw = &W[(size_t)(col0 + row) * K + kt + kq * 8];
            asm volatile("cp.async.cg.shared.global [%0], [%1], 16;"
                         :: "r"(db), "l"(gw));
        }
        asm volatile("cp.async.commit_group;");
    };

    issue(0);
    issue(1);
    for (int tile = 0; tile < nTiles; ++tile) {
        if (tile + 2 < nTiles) {
            issue(tile + 2);
            asm volatile("cp.async.wait_group 2;");
        } else if (tile + 1 < nTiles) {
            asm volatile("cp.async.wait_group 1;");
        } else {
            asm volatile("cp.async.wait_group 0;");
        }
        __syncthreads();                        // single barrier per tile

        const __half* Asb = &smh[(tile & 3) * GTILE];
        const __half* Bsb = &smh[4 * GTILE + (tile & 3) * GTILE];

        #pragma unroll
        for (int kk = 0; kk < 32; kk += 16) {
            uint32_t bf[8][2];
            #pragma unroll
            for (int nt = 0; nt < 8; nt++) {
                int n = wn * 64 + nt * 8 + g;
                bf[nt][0] = *(const uint32_t*)&Bsb[n * GLDS + kk + 2 * tg];
                bf[nt][1] = *(const uint32_t*)&Bsb[n * GLDS + kk + 2 * tg + 8];
            }
            #pragma unroll
            for (int mt = 0; mt < 2; mt++) {
                int r = wm * 32 + mt * 16 + g;
                uint32_t a0 = *(const uint32_t*)&Asb[(r    ) * GLDS + kk + 2 * tg];
                uint32_t a1 = *(const uint32_t*)&Asb[(r + 8) * GLDS + kk + 2 * tg];
                uint32_t a2 = *(const uint32_t*)&Asb[(r    ) * GLDS + kk + 2 * tg + 8];
                uint32_t a3 = *(const uint32_t*)&Asb[(r + 8) * GLDS + kk + 2 * tg + 8];
                #pragma unroll
                for (int nt = 0; nt < 8; nt++)
                    mma_f16(acc[mt][nt], a0, a1, a2, a3, bf[nt][0], bf[nt][1]);
            }
        }
    }

    // epilogue: bias; relu+fp16 store (layers 1-2) or fp32 store (layer 3)
    #pragma unroll
    for (int mt = 0; mt < 2; mt++) {
        int r = row0 + wm * 32 + mt * 16 + g;
        #pragma unroll
        for (int nt = 0; nt < 8; nt++) {
            int col = col0 + wn * 64 + nt * 8 + tg * 2;
            float2 bv = *(const float2*)&bias[col];
            float v0 = acc[mt][nt][0] + bv.x;
            float v1 = acc[mt][nt][1] + bv.y;
            float v2 = acc[mt][nt][2] + bv.x;
            float v3 = acc[mt][nt][3] + bv.y;
            if (relu_half) {
                __half* C = (__half*)Cout;
                __half2 h0 = __floats2half2_rn(fmaxf(v0, 0.f), fmaxf(v1, 0.f));
                __half2 h1 = __floats2half2_rn(fmaxf(v2, 0.f), fmaxf(v3, 0.f));
                if (r < N_NODES)     *(__half2*)&C[(size_t)r * HID + col]       = h0;
                if (r + 8 < N_NODES) *(__half2*)&C[(size_t)(r + 8) * HID + col] = h1;
            } else {
                float* C = (float*)Cout;
                if (r < N_NODES)     *(float2*)&C[(size_t)r * HID + col]       = make_float2(v0, v1);
                if (r + 8 < N_NODES) *(float2*)&C[(size_t)(r + 8) * HID + col] = make_float2(v2, v3);
            }
        }
    }
}

// ---------------- launch ----------------
extern "C" void kernel_launch(void* const* d_in, const int* in_sizes, int n_in,
                              void* d_out, int out_size) {
    const float* x   = (const float*)d_in[0];
    const int*   eiw = (const int*)d_in[1];
    const float* Wl1 = (const float*)d_in[2];
    const float* Wr1 = (const float*)d_in[3];
    const float* b1  = (const float*)d_in[4];
    const float* Wl2 = (const float*)d_in[5];
    const float* Wr2 = (const float*)d_in[6];
    const float* b2  = (const float*)d_in[7];
    const float* Wl3 = (const float*)d_in[8];
    const float* Wr3 = (const float*)d_in[9];
    const float* b3  = (const float*)d_in[10];
    float*       out = (float*)d_out;

    __half *agg, *h, *h2, *xh, *wh;
    cudaGetSymbolAddress((void**)&agg, g_agg);
    cudaGetSymbolAddress((void**)&h,   g_h);
    cudaGetSymbolAddress((void**)&h2,  g_h2);
    cudaGetSymbolAddress((void**)&xh,  g_xh);
    cudaGetSymbolAddress((void**)&wh,  g_wh);

    cudaFuncSetAttribute(k_gemm_h,
                         cudaFuncAttributeMaxDynamicSharedMemorySize, GSMEM);

    // CSR build + fp16 conversion
    k_init<<<(N_NODES + 255) / 256, 256>>>(eiw);
    k_extract_count<<<(N_EDGES + 255) / 256, 256>>>(eiw);
    k_scan_phase1<<<SCAN_BLOCKS, 1024>>>();
    k_scan_phase23<<<SCAN_BLOCKS, 1024>>>();
    k_fill_src<<<(N_EDGES + 255) / 256, 256>>>();
    k_convert<<<(NX + W_TOTAL + 255) / 256, 256>>>(x, Wl1, Wr1, Wl2, Wr2, Wl3, Wr3);

    dim3 ggrid((N_NODES + 127) / 128, HID / 128);   // 313 x 2

    // Layer 1: 128 -> 256, relu, fp16 out
    k_aggregate_h<IN_DIM><<<(N_NODES + 15) / 16, 256>>>(xh, agg);
    k_gemm_h<<<ggrid, 256, GSMEM>>>(agg, wh + WO_L1, xh, wh + WO_R1,
                                    IN_DIM, b1, h, 1);

    // Layer 2: 256 -> 256, relu, fp16 out
    k_aggregate_h<HID><<<(N_NODES + 7) / 8, 256>>>(h, agg);
    k_gemm_h<<<ggrid, 256, GSMEM>>>(agg, wh + WO_L2, h, wh + WO_R2,
                                    HID, b2, h2, 1);

    // Layer 3: 256 -> 256, fp32 out to d_out
    k_aggregate_h<HID><<<(N_NODES + 7) / 8, 256>>>(h2, agg);
    k_gemm_h<<<ggrid, 256, GSMEM>>>(agg, wh + WO_L3, h2, wh + WO_R3,
                                    HID, b3, out, 0);
}

// round 13
// speedup vs baseline: 1.6943x; 1.0496x over previous
#include <cuda_runtime.h>
#include <cuda_fp16.h>
#include <cstdint>

#define N_NODES 40000
#define N_EDGES 640000
#define IN_DIM  128
#define HID     256

#define SCAN_BLOCKS 40
#define SCAN_CHUNK  1000   // 40 * 1000 = 40000 exactly

// ---------------- device scratch (static, no allocations) ----------------
__device__ int   g_is64;
__device__ int   g_srcs[N_EDGES];
__device__ int   g_dsts[N_EDGES];
__device__ int   g_count[N_NODES];
__device__ int   g_rowstart[N_NODES + 1];
__device__ int   g_cursor[N_NODES];
__device__ int   g_src[N_EDGES];
__device__ int   g_blocksum[SCAN_BLOCKS];

#define WO_L1 0
#define WO_R1 (HID * IN_DIM)
#define WO_L2 (2 * HID * IN_DIM)
#define WO_R2 (2 * HID * IN_DIM + HID * HID)
#define WO_L3 (2 * HID * IN_DIM + 2 * HID * HID)
#define WO_R3 (2 * HID * IN_DIM + 3 * HID * HID)
#define W_TOTAL (2 * HID * IN_DIM + 4 * HID * HID)
#define NX (N_NODES * IN_DIM)

__device__ __align__(16) __half g_xh [(size_t)NX];
__device__ __align__(16) __half g_wh [W_TOTAL];
__device__ __align__(16) __half g_agg[(size_t)N_NODES * HID];
__device__ __align__(16) __half g_h  [(size_t)N_NODES * HID];
__device__ __align__(16) __half g_h2 [(size_t)N_NODES * HID];

// ---------------- fused init: zero counts + dtype detect + fp16 convert -----
__global__ void k_init_convert(const int* __restrict__ ei_w,
                               const float* __restrict__ x,
                               const float* __restrict__ Wl1, const float* __restrict__ Wr1,
                               const float* __restrict__ Wl2, const float* __restrict__ Wr2,
                               const float* __restrict__ Wl3, const float* __restrict__ Wr3) {
    int i = blockIdx.x * blockDim.x + threadIdx.x;
    if (i < N_NODES) g_count[i] = 0;
    if (blockIdx.x == 0) {
        __shared__ int acc;
        if (threadIdx.x == 0) acc = 0;
        __syncthreads();
        int v = 0;
        for (int j = threadIdx.x; j < 2048; j += 256) v |= ei_w[2 * j + 1];
        atomicOr(&acc, v);
        __syncthreads();
        if (threadIdx.x == 0) g_is64 = (acc == 0) ? 1 : 0;
    }
    if (i < NX) {
        g_xh[i] = __float2half_rn(x[i]);
        return;
    }
    int j = i - NX;
    if (j >= W_TOTAL) return;
    float v;
    if      (j < WO_R1) v = Wl1[j - WO_L1];
    else if (j < WO_L2) v = Wr1[j - WO_R1];
    else if (j < WO_R2) v = Wl2[j - WO_L2];
    else if (j < WO_L3) v = Wr2[j - WO_R2];
    else if (j < WO_R3) v = Wl3[j - WO_L3];
    else                v = Wr3[j - WO_R3];
    g_wh[j] = __float2half_rn(v);
}

__device__ __forceinline__ int clampN(int v) {
    return v < 0 ? 0 : (v >= N_NODES ? N_NODES - 1 : v);
}

__global__ void k_extract_count(const int* __restrict__ ei_w) {
    int e = blockIdx.x * blockDim.x + threadIdx.x;
    if (e >= N_EDGES) return;
    int s, d;
    if (g_is64) {
        s = ei_w[2 * (size_t)e];
        d = ei_w[2 * ((size_t)N_EDGES + e)];
    } else {
        s = ei_w[e];
        d = ei_w[N_EDGES + e];
    }
    s = clampN(s); d = clampN(d);
    g_srcs[e] = s;
    g_dsts[e] = d;
    atomicAdd(&g_count[d], 1);
}

// ---------------- decoupled scan ----------------
__global__ void k_scan_phase1() {
    __shared__ int sm[1024];
    const int b = blockIdx.x, t = threadIdx.x;
    const int idx = b * SCAN_CHUNK + t;
    int v = (t < SCAN_CHUNK) ? g_count[idx] : 0;
    sm[t] = v;
    __syncthreads();
    for (int off = 1; off < 1024; off <<= 1) {
        int u = (t >= off) ? sm[t - off] : 0;
        __syncthreads();
        sm[t] += u;
        __syncthreads();
    }
    if (t < SCAN_CHUNK) g_rowstart[idx] = sm[t] - v;
    if (t == 1023) g_blocksum[b] = sm[1023];
}

__global__ void k_scan_phase23() {
    __shared__ int off_total[2];
    const int b = blockIdx.x, t = threadIdx.x;
    if (t == 0) {
        int run = 0;
        for (int i = 0; i < SCAN_BLOCKS; i++) {
            if (i == b) off_total[0] = run;
            run += g_blocksum[i];
        }
        off_total[1] = run;
    }
    __syncthreads();
    if (t < SCAN_CHUNK) {
        int idx = b * SCAN_CHUNK + t;
        int rs = g_rowstart[idx] + off_total[0];
        g_rowstart[idx] = rs;
        g_cursor[idx]   = rs;
    }
    if (b == 0 && t == 0) g_rowstart[N_NODES] = off_total[1];
}

__global__ void k_fill_src() {
    int e = blockIdx.x * blockDim.x + threadIdx.x;
    if (e < N_EDGES) {
        int pos = atomicAdd(&g_cursor[g_dsts[e]], 1);
        g_src[pos] = g_srcs[e];
    }
}

// ---------------- mean aggregation over in-edges (fp16 in/out, fp32 acc) ----
// 8-edge unroll -> 8 outstanding 16B loads per thread for latency hiding.
template <int D>
__global__ void k_aggregate_h(const __half* __restrict__ x, __half* __restrict__ out) {
    constexpr int TPN = D / 8;        // threads per node, uint4 = 8 halves
    constexpr int NPB = 256 / TPN;
    int node = blockIdx.x * NPB + threadIdx.x / TPN;
    int lane = threadIdx.x % TPN;
    if (node >= N_NODES) return;

    const int beg = g_rowstart[node];
    const int end = g_rowstart[node + 1];
    const uint4* xv = (const uint4*)x;

    float acc[8] = {};
    int j = beg;
    for (; j + 8 <= end; j += 8) {
        uint4 v[8];
        #pragma unroll
        for (int e = 0; e < 8; e++)
            v[e] = xv[(size_t)g_src[j + e] * TPN + lane];
        #pragma unroll
        for (int e = 0; e < 8; e++) {
            #pragma unroll
            for (int q = 0; q < 4; q++) {
                uint32_t w = (&v[e].x)[q];
                float2 f = __half22float2(*(__half2*)&w);
                acc[2 * q + 0] += f.x;
                acc[2 * q + 1] += f.y;
            }
        }
    }
    for (; j + 4 <= end; j += 4) {
        uint4 v[4];
        #pragma unroll
        for (int e = 0; e < 4; e++)
            v[e] = xv[(size_t)g_src[j + e] * TPN + lane];
        #pragma unroll
        for (int e = 0; e < 4; e++) {
            #pragma unroll
            for (int q = 0; q < 4; q++) {
                uint32_t w = (&v[e].x)[q];
                float2 f = __half22float2(*(__half2*)&w);
                acc[2 * q + 0] += f.x;
                acc[2 * q + 1] += f.y;
            }
        }
    }
    for (; j < end; j++) {
        uint4 v = xv[(size_t)g_src[j] * TPN + lane];
        #pragma unroll
        for (int q = 0; q < 4; q++) {
            uint32_t w = (&v.x)[q];
            float2 f = __half22float2(*(__half2*)&w);
            acc[2 * q + 0] += f.x;
            acc[2 * q + 1] += f.y;
        }
    }
    float inv = (end > beg) ? 1.f / (float)(end - beg) : 0.f;
    uint4 r;
    #pragma unroll
    for (int q = 0; q < 4; q++) {
        __half2 hp = __floats2half2_rn(acc[2 * q] * inv, acc[2 * q + 1] * inv);
        (&r.x)[q] = *(uint32_t*)&hp;
    }
    ((uint4*)out)[(size_t)node * TPN + lane] = r;
}

// ---------------- fp16 tensor-core fused dual-source GEMM (R11, proven) -----
// C[M,256] = A0@W0^T + A1@W1^T + b (optional ReLU); fp32 accumulate.
// BM=BN=128, BK=32 halves; 4-stage cp.async, issue distance 2, one barrier/tile.
__device__ __forceinline__ void mma_f16(float* c,
                                        uint32_t a0, uint32_t a1, uint32_t a2, uint32_t a3,
                                        uint32_t b0, uint32_t b1) {
    asm volatile(
        "mma.sync.aligned.m16n8k16.row.col.f32.f16.f16.f32 "
        "{%0,%1,%2,%3}, {%4,%5,%6,%7}, {%8,%9}, {%0,%1,%2,%3};"
        : "+f"(c[0]), "+f"(c[1]), "+f"(c[2]), "+f"(c[3])
        : "r"(a0), "r"(a1), "r"(a2), "r"(a3), "r"(b0), "r"(b1));
}

#define GLDS  40                       // halves per smem row (80 B)
#define GTILE (128 * GLDS)             // halves per stage buffer (10 KB)
#define GSMEM (8 * GTILE * 2)          // 4 A stages + 4 B stages = 81920 B

__global__ __launch_bounds__(256, 2)
void k_gemm_h(const __half* __restrict__ A0, const __half* __restrict__ W0,
              const __half* __restrict__ A1, const __half* __restrict__ W1,
              int K, const float* __restrict__ bias,
              void* __restrict__ Cout, int relu_half) {
    extern __shared__ __half smh[];    // [As0..As3 | Bs0..Bs3]

    const int t    = threadIdx.x;
    const int warp = t >> 5, lane = t & 31;
    const int g    = lane >> 2, tg = lane & 3;
    const int wm   = warp & 3;                 // M offset 32*wm
    const int wn   = warp >> 2;                // N offset 64*wn
    const int row0 = blockIdx.x * 128;
    const int col0 = blockIdx.y * 128;

    const int lr = t >> 2;                     // 0..63 load row (2 passes)
    const int kq = t & 3;                      // 0..3, 16B (8-half) chunk

    const int tilesPerSrc = K >> 5;
    const int nTiles = 2 * tilesPerSrc;

    float acc[2][8][4] = {};

    auto issue = [&](int tile) {
        const int s = tile & 3;
        const __half* A = (tile < tilesPerSrc) ? A0 : A1;
        const __half* W = (tile < tilesPerSrc) ? W0 : W1;
        const int kt = ((tile < tilesPerSrc) ? tile : tile - tilesPerSrc) << 5;
        #pragma unroll
        for (int p = 0; p < 2; p++) {
            int row = lr + 64 * p;
            uint32_t da = (uint32_t)__cvta_generic_to_shared(
                &smh[s * GTILE + row * GLDS + kq * 8]);
            const __half* ga = &A[(size_t)(row0 + row) * K + kt + kq * 8];
            int sz = (row0 + row < N_NODES) ? 16 : 0;
            asm volatile("cp.async.cg.shared.global [%0], [%1], 16, %2;"
                         :: "r"(da), "l"(ga), "r"(sz));
            uint32_t db = (uint32_t)__cvta_generic_to_shared(
                &smh[4 * GTILE + s * GTILE + row * GLDS + kq * 8]);
            const __half* gw = &W[(size_t)(col0 + row) * K + kt + kq * 8];
            asm volatile("cp.async.cg.shared.global [%0], [%1], 16;"
                         :: "r"(db), "l"(gw));
        }
        asm volatile("cp.async.commit_group;");
    };

    issue(0);
    issue(1);
    for (int tile = 0; tile < nTiles; ++tile) {
        if (tile + 2 < nTiles) {
            issue(tile + 2);
            asm volatile("cp.async.wait_group 2;");
        } else if (tile + 1 < nTiles) {
            asm volatile("cp.async.wait_group 1;");
        } else {
            asm volatile("cp.async.wait_group 0;");
        }
        __syncthreads();                        // single barrier per tile

        const __half* Asb = &smh[(tile & 3) * GTILE];
        const __half* Bsb = &smh[4 * GTILE + (tile & 3) * GTILE];

        #pragma unroll
        for (int kk = 0; kk < 32; kk += 16) {
            uint32_t bf[8][2];
            #pragma unroll
            for (int nt = 0; nt < 8; nt++) {
                int n = wn * 64 + nt * 8 + g;
                bf[nt][0] = *(const uint32_t*)&Bsb[n * GLDS + kk + 2 * tg];
                bf[nt][1] = *(const uint32_t*)&Bsb[n * GLDS + kk + 2 * tg + 8];
            }
            #pragma unroll
            for (int mt = 0; mt < 2; mt++) {
                int r = wm * 32 + mt * 16 + g;
                uint32_t a0 = *(const uint32_t*)&Asb[(r    ) * GLDS + kk + 2 * tg];
                uint32_t a1 = *(const uint32_t*)&Asb[(r + 8) * GLDS + kk + 2 * tg];
                uint32_t a2 = *(const uint32_t*)&Asb[(r    ) * GLDS + kk + 2 * tg + 8];
                uint32_t a3 = *(const uint32_t*)&Asb[(r + 8) * GLDS + kk + 2 * tg + 8];
                #pragma unroll
                for (int nt = 0; nt < 8; nt++)
                    mma_f16(acc[mt][nt], a0, a1, a2, a3, bf[nt][0], bf[nt][1]);
            }
        }
    }

    // epilogue: bias; relu+fp16 store (layers 1-2) or fp32 store (layer 3)
    #pragma unroll
    for (int mt = 0; mt < 2; mt++) {
        int r = row0 + wm * 32 + mt * 16 + g;
        #pragma unroll
        for (int nt = 0; nt < 8; nt++) {
            int col = col0 + wn * 64 + nt * 8 + tg * 2;
            float2 bv = *(const float2*)&bias[col];
            float v0 = acc[mt][nt][0] + bv.x;
            float v1 = acc[mt][nt][1] + bv.y;
            float v2 = acc[mt][nt][2] + bv.x;
            float v3 = acc[mt][nt][3] + bv.y;
            if (relu_half) {
                __half* C = (__half*)Cout;
                __half2 h0 = __floats2half2_rn(fmaxf(v0, 0.f), fmaxf(v1, 0.f));
                __half2 h1 = __floats2half2_rn(fmaxf(v2, 0.f), fmaxf(v3, 0.f));
                if (r < N_NODES)     *(__half2*)&C[(size_t)r * HID + col]       = h0;
                if (r + 8 < N_NODES) *(__half2*)&C[(size_t)(r + 8) * HID + col] = h1;
            } else {
                float* C = (float*)Cout;
                if (r < N_NODES)     *(float2*)&C[(size_t)r * HID + col]       = make_float2(v0, v1);
                if (r + 8 < N_NODES) *(float2*)&C[(size_t)(r + 8) * HID + col] = make_float2(v2, v3);
            }
        }
    }
}

// ---------------- launch ----------------
extern "C" void kernel_launch(void* const* d_in, const int* in_sizes, int n_in,
                              void* d_out, int out_size) {
    const float* x   = (const float*)d_in[0];
    const int*   eiw = (const int*)d_in[1];
    const float* Wl1 = (const float*)d_in[2];
    const float* Wr1 = (const float*)d_in[3];
    const float* b1  = (const float*)d_in[4];
    const float* Wl2 = (const float*)d_in[5];
    const float* Wr2 = (const float*)d_in[6];
    const float* b2  = (const float*)d_in[7];
    const float* Wl3 = (const float*)d_in[8];
    const float* Wr3 = (const float*)d_in[9];
    const float* b3  = (const float*)d_in[10];
    float*       out = (float*)d_out;

    __half *agg, *h, *h2, *xh, *wh;
    cudaGetSymbolAddress((void**)&agg, g_agg);
    cudaGetSymbolAddress((void**)&h,   g_h);
    cudaGetSymbolAddress((void**)&h2,  g_h2);
    cudaGetSymbolAddress((void**)&xh,  g_xh);
    cudaGetSymbolAddress((void**)&wh,  g_wh);

    cudaFuncSetAttribute(k_gemm_h,
                         cudaFuncAttributeMaxDynamicSharedMemorySize, GSMEM);

    // fused init (zero counts + detect + fp16 convert), then CSR build
    k_init_convert<<<(NX + W_TOTAL + 255) / 256, 256>>>(eiw, x, Wl1, Wr1,
                                                        Wl2, Wr2, Wl3, Wr3);
    k_extract_count<<<(N_EDGES + 255) / 256, 256>>>(eiw);
    k_scan_phase1<<<SCAN_BLOCKS, 1024>>>();
    k_scan_phase23<<<SCAN_BLOCKS, 1024>>>();
    k_fill_src<<<(N_EDGES + 255) / 256, 256>>>();

    dim3 ggrid((N_NODES + 127) / 128, HID / 128);   // 313 x 2

    // Layer 1: 128 -> 256, relu, fp16 out
    k_aggregate_h<IN_DIM><<<(N_NODES + 15) / 16, 256>>>(xh, agg);
    k_gemm_h<<<ggrid, 256, GSMEM>>>(agg, wh + WO_L1, xh, wh + WO_R1,
                                    IN_DIM, b1, h, 1);

    // Layer 2: 256 -> 256, relu, fp16 out
    k_aggregate_h<HID><<<(N_NODES + 7) / 8, 256>>>(h, agg);
    k_gemm_h<<<ggrid, 256, GSMEM>>>(agg, wh + WO_L2, h, wh + WO_R2,
                                    HID, b2, h2, 1);

    // Layer 3: 256 -> 256, fp32 out to d_out
    k_aggregate_h<HID><<<(N_NODES + 7) / 8, 256>>>(h2, agg);
    k_gemm_h<<<ggrid, 256, GSMEM>>>(agg, wh + WO_L3, h2, wh + WO_R3,
                                    HID, b3, out, 0);
}